// round 7
// baseline (speedup 1.0000x reference)
#include <cuda_runtime.h>
#include <cstdint>
#include <math.h>

#define NB_ 64
#define NS_ 512
#define NHID_ 256
#define NTAGS_ 9
#define LOGITS_N (NB_ * NS_ * NTAGS_)   // 294912
#define LENS_OFF LOGITS_N               // 294912
#define LL_OFF   (LOGITS_N + NB_)       // 294976

// Scratch (device globals: no allocation allowed)
__device__ float g_xzf[NB_ * NS_ * 1024];   // x @ W_f + b_f
__device__ float g_xzb[NB_ * NS_ * 1024];   // x @ W_b + b_b
__device__ float g_hf[NB_ * NS_ * NHID_];
__device__ float g_hb[NB_ * NS_ * NHID_];

// ---------------- packed f32x2 helpers (sm_103a FFMA2 path) ----------------
__device__ __forceinline__ unsigned long long pk2(float lo, float hi) {
    unsigned long long r;
    asm("mov.b64 %0, {%1, %2};" : "=l"(r) : "f"(lo), "f"(hi));
    return r;
}
__device__ __forceinline__ float2 unpk2(unsigned long long v) {
    float2 r;
    asm("mov.b64 {%0, %1}, %2;" : "=f"(r.x), "=f"(r.y) : "l"(v));
    return r;
}
__device__ __forceinline__ unsigned long long fma2_(unsigned long long a,
                                                    unsigned long long b,
                                                    unsigned long long c) {
    unsigned long long d;
    asm("fma.rn.f32x2 %0, %1, %2, %3;" : "=l"(d) : "l"(a), "l"(b), "l"(c));
    return d;
}
__device__ __forceinline__ unsigned long long add2_(unsigned long long a,
                                                    unsigned long long b) {
    unsigned long long d;
    asm("add.rn.f32x2 %0, %1, %2;" : "=l"(d) : "l"(a), "l"(b));
    return d;
}

__device__ __forceinline__ float fsig(float x) {
    return __fdividef(1.0f, 1.0f + __expf(-x));
}
__device__ __forceinline__ float ftanh_(float x) {
    x = fminf(fmaxf(x, -15.0f), 15.0f);
    float e = __expf(2.0f * x);
    return __fdividef(e - 1.0f, e + 1.0f);
}

// ---------------------------------------------------------------------------
// Dummy kernel: shifts the ncu capture window (-s 5 -c 1) so that k_lstm
// lands on the profiled launch slot. Negligible runtime.
// ---------------------------------------------------------------------------
__device__ int g_dummy_sink;
__global__ void k_nop(int v) { if (threadIdx.x == 1025) g_dummy_sink = v; }

// ---------------------------------------------------------------------------
// K1: fused embedding-gather + input GEMM (A duplicated in smem, u64 B pairs).
// ---------------------------------------------------------------------------
__global__ void __launch_bounds__(256, 2)
k_ingemm(const int* __restrict__ text, const float* __restrict__ emb,
         const float* __restrict__ Wf, const float* __restrict__ bf,
         const float* __restrict__ Wb, const float* __restrict__ bb)
{
    extern __shared__ char sm1raw[];
    unsigned long long* As2 = (unsigned long long*)sm1raw;   // 64 x 130 u64
    float* Bs = (float*)(As2 + 64 * 130);                    // 128 x 64 f32
    int*   toks = (int*)(Bs + 128 * 64);                     // 64

    int bx = blockIdx.x, by = blockIdx.y, tid = threadIdx.x;
    const float* W; const float* bias; float* out; int ncol0;
    if (by < 16) { W = Wf; bias = bf; out = g_xzf; ncol0 = by * 64; }
    else         { W = Wb; bias = bb; out = g_xzb; ncol0 = (by - 16) * 64; }

    if (tid < 64) toks[tid] = text[bx * 64 + tid];
    __syncthreads();

    for (int i = tid; i < 2048; i += 256) {
        int m = i >> 5, k4 = i & 31;
        float4 v = __ldg((const float4*)(emb + (size_t)toks[m] * 128) + k4);
        ulonglong2 d0, d1;
        d0.x = pk2(v.x, v.x); d0.y = pk2(v.y, v.y);
        d1.x = pk2(v.z, v.z); d1.y = pk2(v.w, v.w);
        *(ulonglong2*)(As2 + m * 130 + k4 * 4)     = d0;
        *(ulonglong2*)(As2 + m * 130 + k4 * 4 + 2) = d1;
    }
    for (int i = tid; i < 2048; i += 256) {
        int k = i >> 4, n4 = i & 15;
        float4 v = __ldg((const float4*)(W + (size_t)k * 1024 + ncol0) + n4);
        *(float4*)(Bs + k * 64 + n4 * 4) = v;
    }
    __syncthreads();

    int tx = tid & 15, ty = tid >> 4;
    const unsigned long long* Bu = (const unsigned long long*)Bs;
    unsigned long long a01[4], a23[4];
#pragma unroll
    for (int i = 0; i < 4; i++) { a01[i] = 0ULL; a23[i] = 0ULL; }

#pragma unroll 2
    for (int kb = 0; kb < 128; kb += 4) {
        ulonglong2 ar0[4], ar1[4];
#pragma unroll
        for (int i = 0; i < 4; i++) {
            ar0[i] = *(const ulonglong2*)(As2 + (ty * 4 + i) * 130 + kb);
            ar1[i] = *(const ulonglong2*)(As2 + (ty * 4 + i) * 130 + kb + 2);
        }
#pragma unroll
        for (int kq = 0; kq < 4; kq++) {
            ulonglong2 b2 = *(const ulonglong2*)(Bu + (size_t)(kb + kq) * 32 + tx * 2);
#pragma unroll
            for (int i = 0; i < 4; i++) {
                unsigned long long ad = (kq == 0) ? ar0[i].x : (kq == 1) ? ar0[i].y
                                      : (kq == 2) ? ar1[i].x : ar1[i].y;
                a01[i] = fma2_(ad, b2.x, a01[i]);
                a23[i] = fma2_(ad, b2.y, a23[i]);
            }
        }
    }

    float4 bvv = *(const float4*)(bias + ncol0 + tx * 4);
#pragma unroll
    for (int i = 0; i < 4; i++) {
        float2 p01 = unpk2(a01[i]), p23 = unpk2(a23[i]);
        float4 o;
        o.x = p01.x + bvv.x; o.y = p01.y + bvv.y;
        o.z = p23.x + bvv.z; o.w = p23.y + bvv.w;
        *(float4*)(out + (size_t)(bx * 64 + ty * 4 + i) * 1024 + ncol0 + tx * 4) = o;
    }
}

// ---------------------------------------------------------------------------
// K2: LSTM recurrence. 16 clusters x 8 CTAs. Conflict-free smem layouts.
// Consumer->pusher handoff uses named barrier (warps 0-7 only); GEMM-only
// warps 8-15 skip it and head straight to the cluster arrive.
// ---------------------------------------------------------------------------
__global__ void __cluster_dims__(8, 1, 1) __launch_bounds__(512, 1)
k_lstm(const float* __restrict__ Uf, const float* __restrict__ Ub)
{
    extern __shared__ float sm2[];
    float* Uc  = sm2;                                        // 256 x 128 = 128KB
    float* hbt = sm2 + 32768;                                // 2 x 256 x 8 = 16KB
    ulonglong2* zpu2 = (ulonglong2*)(hbt + 4096);            // 4096 x 16B = 64KB
    unsigned long long* stg = (unsigned long long*)(zpu2 + 4096); // 128 u64 = 1KB

    int tid = threadIdx.x;
    unsigned rank;
    asm("mov.u32 %0, %%cluster_ctarank;" : "=r"(rank));
    int cl = blockIdx.x >> 3;
    int dir = cl & 1, bg = cl >> 1;
    const float* U    = dir ? Ub     : Uf;
    const float* xz   = dir ? g_xzb  : g_xzf;
    float*       hout = dir ? g_hb   : g_hf;

    int w = tid >> 5, l = tid & 31;
    int k0 = w * 16;

    for (int idx = tid; idx < 32768; idx += 512) {
        int k = idx >> 7, c = idx & 127;
        int unit = c >> 2, g = c & 3;
        Uc[idx] = __ldg(U + (size_t)k * 1024 + g * 256 + rank * 32 + unit);
    }
    for (int i = tid; i < 4096; i += 512) hbt[i] = 0.0f;

    bool cons = (w < 4);
    int bp = w, jj = l;
    int b0 = bg * 8 + 2 * bp, b1 = b0 + 1;
    float cst0 = 0.f, cst1 = 0.f, h0new = 0.f, h1new = 0.f;
    float x[8];
    const float* xbase0 = xz + (size_t)b0 * 512 * 1024 + rank * 32 + jj;
    const float* xbase1 = xz + (size_t)b1 * 512 * 1024 + rank * 32 + jj;
    float* hob0 = hout + (size_t)b0 * 512 * 256 + rank * 32 + jj;
    float* hob1 = hout + (size_t)b1 * 512 * 256 + rank * 32 + jj;
    if (cons) {
        int t0 = dir ? 511 : 0;
        const float* xp0 = xbase0 + (size_t)t0 * 1024;
        const float* xp1 = xbase1 + (size_t)t0 * 1024;
        x[0] = __ldg(xp0); x[1] = __ldg(xp0 + 256); x[2] = __ldg(xp0 + 512); x[3] = __ldg(xp0 + 768);
        x[4] = __ldg(xp1); x[5] = __ldg(xp1 + 256); x[6] = __ldg(xp1 + 512); x[7] = __ldg(xp1 + 768);
    }
    bool push_w = (w >= 4 && w < 8);
    int m = tid - 128;
    uint32_t ra[8];
    if (push_w) {
        int pjj = m >> 2, pbp = m & 3;
        uint32_t hb_addr = (uint32_t)__cvta_generic_to_shared(hbt);
        uint32_t loff = hb_addr + (uint32_t)(((rank * 32 + pjj) * 8 + 2 * pbp) * 4);
#pragma unroll
        for (int dc = 0; dc < 8; dc++)
            asm volatile("mapa.shared::cluster.u32 %0, %1, %2;" : "=r"(ra[dc]) : "r"(loff), "r"(dc));
    }
    asm volatile("barrier.cluster.arrive.aligned;\n\tbarrier.cluster.wait.aligned;" ::: "memory");

    for (int n = 0; n < 512; n++) {
        int cur = n & 1, nxt = cur ^ 1;
        int t = dir ? (511 - n) : n;

        const float* hc = hbt + cur * 2048;
        unsigned long long acc[4][4];
#pragma unroll
        for (int p = 0; p < 4; p++)
#pragma unroll
            for (int g = 0; g < 4; g++) acc[p][g] = 0ULL;

#pragma unroll
        for (int kk = 0; kk < 16; kk++) {
            int k = k0 + kk;
            float4 uq = *(const float4*)(Uc + k * 128 + l * 4);
            unsigned long long u0 = pk2(uq.x, uq.x);
            unsigned long long u1 = pk2(uq.y, uq.y);
            unsigned long long u2 = pk2(uq.z, uq.z);
            unsigned long long u3 = pk2(uq.w, uq.w);
            ulonglong2 hA = *(const ulonglong2*)(hc + k * 8);
            ulonglong2 hB = *(const ulonglong2*)(hc + k * 8 + 4);
            acc[0][0] = fma2_(hA.x, u0, acc[0][0]); acc[0][1] = fma2_(hA.x, u1, acc[0][1]);
            acc[0][2] = fma2_(hA.x, u2, acc[0][2]); acc[0][3] = fma2_(hA.x, u3, acc[0][3]);
            acc[1][0] = fma2_(hA.y, u0, acc[1][0]); acc[1][1] = fma2_(hA.y, u1, acc[1][1]);
            acc[1][2] = fma2_(hA.y, u2, acc[1][2]); acc[1][3] = fma2_(hA.y, u3, acc[1][3]);
            acc[2][0] = fma2_(hB.x, u0, acc[2][0]); acc[2][1] = fma2_(hB.x, u1, acc[2][1]);
            acc[2][2] = fma2_(hB.x, u2, acc[2][2]); acc[2][3] = fma2_(hB.x, u3, acc[2][3]);
            acc[3][0] = fma2_(hB.y, u0, acc[3][0]); acc[3][1] = fma2_(hB.y, u1, acc[3][1]);
            acc[3][2] = fma2_(hB.y, u2, acc[3][2]); acc[3][3] = fma2_(hB.y, u3, acc[3][3]);
        }
#pragma unroll
        for (int p = 0; p < 4; p++) {
            ulonglong2 h0v, h1v;
            h0v.x = acc[p][0]; h0v.y = acc[p][1];
            h1v.x = acc[p][2]; h1v.y = acc[p][3];
            zpu2[((w * 4 + p) * 2 + 0) * 32 + l] = h0v;
            zpu2[((w * 4 + p) * 2 + 1) * 32 + l] = h1v;
        }
        __syncthreads();

        if (cons) {
            unsigned long long s0 = 0ULL, s1 = 0ULL, s2 = 0ULL, s3 = 0ULL;
#pragma unroll
            for (int w2 = 0; w2 < 16; w2++) {
                ulonglong2 a = zpu2[((w2 * 4 + bp) * 2 + 0) * 32 + jj];
                ulonglong2 b = zpu2[((w2 * 4 + bp) * 2 + 1) * 32 + jj];
                s0 = add2_(s0, a.x); s1 = add2_(s1, a.y);
                s2 = add2_(s2, b.x); s3 = add2_(s3, b.y);
            }
            float2 zi = unpk2(s0), zf = unpk2(s1), zg = unpk2(s2), zo = unpk2(s3);
            float i0 = fsig(zi.x + x[0]), f0 = fsig(zf.x + x[1]);
            float g0 = ftanh_(zg.x + x[2]), o0 = fsig(zo.x + x[3]);
            float i1 = fsig(zi.y + x[4]), f1 = fsig(zf.y + x[5]);
            float g1 = ftanh_(zg.y + x[6]), o1 = fsig(zo.y + x[7]);
            cst0 = f0 * cst0 + i0 * g0;
            cst1 = f1 * cst1 + i1 * g1;
            h0new = o0 * ftanh_(cst0);
            h1new = o1 * ftanh_(cst1);
            stg[jj * 4 + bp] = pk2(h0new, h1new);
        }
        // consumer -> pusher handoff: warps 0-7 only (warps 8-15 skip)
        if (w < 8)
            asm volatile("bar.sync 1, 256;" ::: "memory");

        if (push_w) {
            unsigned long long hv = stg[m];
            uint32_t poff = (uint32_t)(nxt * 2048 * 4);
#pragma unroll
            for (int dc = 0; dc < 8; dc++)
                asm volatile("st.shared::cluster.b64 [%0], %1;"
                             :: "r"(ra[dc] + poff), "l"(hv));
        }
        asm volatile("barrier.cluster.arrive.aligned;" ::: "memory");

        if (cons) {
            hob0[(size_t)t * 256] = h0new;
            hob1[(size_t)t * 256] = h1new;
            if (n + 1 < 512) {
                int tn = dir ? (511 - (n + 1)) : (n + 1);
                const float* xp0 = xbase0 + (size_t)tn * 1024;
                const float* xp1 = xbase1 + (size_t)tn * 1024;
                x[0] = __ldg(xp0); x[1] = __ldg(xp0 + 256);
                x[2] = __ldg(xp0 + 512); x[3] = __ldg(xp0 + 768);
                x[4] = __ldg(xp1); x[5] = __ldg(xp1 + 256);
                x[6] = __ldg(xp1 + 512); x[7] = __ldg(xp1 + 768);
            }
        }
        asm volatile("barrier.cluster.wait.aligned;" ::: "memory");
    }
}

// ---------------------------------------------------------------------------
// K3: logits = [h_fwd ; h_bwd] @ W_d + b_d.  Warp per row, W_d^T in smem.
// ---------------------------------------------------------------------------
__global__ void k_logits(const float* __restrict__ Wd, const float* __restrict__ bd,
                         float* __restrict__ out)
{
    __shared__ float Wds[NTAGS_ * 512];
    __shared__ float bds[NTAGS_];
    int tid = threadIdx.x;
    for (int i = tid; i < 512 * NTAGS_; i += 256) {
        int k = i / NTAGS_, c = i - k * NTAGS_;
        Wds[c * 512 + k] = Wd[i];
    }
    if (tid < NTAGS_) bds[tid] = bd[tid];
    __syncthreads();

    int wid = tid >> 5, l = tid & 31;
    int r = blockIdx.x * 8 + wid;
    const float* pf = g_hf + (size_t)r * 256 + l;
    const float* pb = g_hb + (size_t)r * 256 + l;
    float hf[8], hbv[8];
#pragma unroll
    for (int i = 0; i < 8; i++) { hf[i] = pf[32 * i]; hbv[i] = pb[32 * i]; }

    float parts[NTAGS_];
#pragma unroll
    for (int c = 0; c < NTAGS_; c++) {
        float p = 0.f;
#pragma unroll
        for (int i = 0; i < 8; i++) {
            p = fmaf(hf[i],  Wds[c * 512 + 32 * i + l], p);
            p = fmaf(hbv[i], Wds[c * 512 + 256 + 32 * i + l], p);
        }
        parts[c] = p;
    }
#pragma unroll
    for (int c = 0; c < NTAGS_; c++)
#pragma unroll
        for (int off = 16; off; off >>= 1)
            parts[c] += __shfl_xor_sync(0xffffffffu, parts[c], off);

    if (l == 0) {
#pragma unroll
        for (int c = 0; c < NTAGS_; c++)
            out[(size_t)r * NTAGS_ + c] = parts[c] + bds[c];
    }
}

// ---------------------------------------------------------------------------
// K4: lens + CRF.  One warp per batch element; fast-math exp/log.
// ---------------------------------------------------------------------------
__global__ void k_crf(const int* __restrict__ text, const int* __restrict__ labels,
                      const float* __restrict__ trans, float* __restrict__ out)
{
    int b = blockIdx.x;
    int l = threadIdx.x;
    const float* lgb = out + (size_t)b * NS_ * NTAGS_;
    const int*   lab = labels + b * NS_;

    int cnt = 0;
#pragma unroll
    for (int i = 0; i < 16; i++) cnt += (text[b * NS_ + l + 32 * i] != 0) ? 1 : 0;
#pragma unroll
    for (int off = 16; off; off >>= 1) cnt += __shfl_xor_sync(0xffffffffu, cnt, off);
    int len = cnt;
    if (l == 0) out[LENS_OFF + b] = (float)len;

    float sc = 0.f;
#pragma unroll
    for (int i = 0; i < 16; i++) {
        int s = l + 32 * i;
        if (s < len)     sc += lgb[s * NTAGS_ + lab[s]];
        if (s < len - 1) sc += trans[lab[s] * NTAGS_ + lab[s + 1]];
    }
#pragma unroll
    for (int off = 16; off; off >>= 1) sc += __shfl_xor_sync(0xffffffffu, sc, off);

    int j = l;
    float tc[NTAGS_];
#pragma unroll
    for (int i = 0; i < NTAGS_; i++) tc[i] = trans[i * NTAGS_ + ((j < NTAGS_) ? j : 0)];
    float alpha = (j < NTAGS_) ? lgb[j] : -3.0e38f;

    float lt_next = (j < NTAGS_) ? lgb[NTAGS_ + j] : 0.f;
    for (int t = 1; t < NS_; t++) {
        float lt = lt_next;
        if (t + 1 < NS_) lt_next = (j < NTAGS_) ? lgb[(t + 1) * NTAGS_ + j] : 0.f;
        float vv[NTAGS_];
#pragma unroll
        for (int i = 0; i < NTAGS_; i++) {
            float ai = __shfl_sync(0xffffffffu, alpha, i);
            vv[i] = ai + tc[i];
        }
        float m01 = fmaxf(vv[0], vv[1]), m23 = fmaxf(vv[2], vv[3]);
        float m45 = fmaxf(vv[4], vv[5]), m67 = fmaxf(vv[6], vv[7]);
        float m03 = fmaxf(m01, m23), m47 = fmaxf(m45, m67);
        float mx = fmaxf(fmaxf(m03, m47), vv[8]);
        float e0 = __expf(vv[0] - mx) + __expf(vv[1] - mx);
        float e1 = __expf(vv[2] - mx) + __expf(vv[3] - mx);
        float e2 = __expf(vv[4] - mx) + __expf(vv[5] - mx);
        float e3 = __expf(vv[6] - mx) + __expf(vv[7] - mx);
        float sume = ((e0 + e1) + (e2 + e3)) + __expf(vv[8] - mx);
        float na = mx + __logf(sume) + lt;
        if ((t < len) && (j < NTAGS_)) alpha = na;
    }

    float a = (j < NTAGS_) ? alpha : -3.0e38f;
    float mx = a;
#pragma unroll
    for (int off = 16; off; off >>= 1) mx = fmaxf(mx, __shfl_xor_sync(0xffffffffu, mx, off));
    float e = (j < NTAGS_) ? __expf(a - mx) : 0.f;
#pragma unroll
    for (int off = 16; off; off >>= 1) e += __shfl_xor_sync(0xffffffffu, e, off);
    float lse = mx + __logf(e);

    if (l == 0) out[LL_OFF + b] = sc - lse;
}

// ---------------------------------------------------------------------------
extern "C" void kernel_launch(void* const* d_in, const int* in_sizes, int n_in,
                              void* d_out, int out_size)
{
    (void)in_sizes; (void)n_in; (void)out_size;
    const int*   text   = (const int*)d_in[0];
    const int*   labels = (const int*)d_in[1];
    const float* emb    = (const float*)d_in[2];
    const float* Wf     = (const float*)d_in[3];
    const float* Uf     = (const float*)d_in[4];
    const float* bf     = (const float*)d_in[5];
    const float* Wb     = (const float*)d_in[6];
    const float* Ub     = (const float*)d_in[7];
    const float* bb     = (const float*)d_in[8];
    const float* Wd     = (const float*)d_in[9];
    const float* bd     = (const float*)d_in[10];
    const float* trans  = (const float*)d_in[11];
    float* out = (float*)d_out;

    int smem1 = 64 * 130 * 8 + 128 * 64 * 4 + 64 * 4;           // 99584 B
    cudaFuncSetAttribute(k_ingemm, cudaFuncAttributeMaxDynamicSharedMemorySize, smem1);
    int smem2 = 32768 * 4 + 4096 * 4 + 4096 * 16 + 128 * 8;     // 128K+16K+64K+1K
    cudaFuncSetAttribute(k_lstm, cudaFuncAttributeMaxDynamicSharedMemorySize, smem2);

    k_ingemm<<<dim3(512, 32), 256, smem1>>>(text, emb, Wf, bf, Wb, bb);
    // two dummy launches so the ncu capture slot (-s 5 -c 1) lands on k_lstm
    k_nop<<<1, 32>>>(0);
    k_nop<<<1, 32>>>(1);
    k_lstm<<<128, 512, smem2>>>(Uf, Ub);
    k_logits<<<4096, 256>>>(Wd, bd, out);
    k_crf<<<NB_, 32>>>(text, labels, trans, out);
}

// round 8
// speedup vs baseline: 1.4724x; 1.4724x over previous
#include <cuda_runtime.h>
#include <cstdint>
#include <math.h>

#define NB_ 64
#define NS_ 512
#define NHID_ 256
#define NTAGS_ 9
#define LOGITS_N (NB_ * NS_ * NTAGS_)   // 294912
#define LENS_OFF LOGITS_N               // 294912
#define LL_OFF   (LOGITS_N + NB_)       // 294976

// Scratch (device globals: no allocation allowed)
__device__ float g_xzf[NB_ * NS_ * 1024];   // x @ W_f + b_f
__device__ float g_xzb[NB_ * NS_ * 1024];   // x @ W_b + b_b
__device__ float g_hf[NB_ * NS_ * NHID_];
__device__ float g_hb[NB_ * NS_ * NHID_];

// ---------------- packed f32x2 helpers (sm_103a FFMA2 path) ----------------
__device__ __forceinline__ unsigned long long pk2(float lo, float hi) {
    unsigned long long r;
    asm("mov.b64 %0, {%1, %2};" : "=l"(r) : "f"(lo), "f"(hi));
    return r;
}
__device__ __forceinline__ float2 unpk2(unsigned long long v) {
    float2 r;
    asm("mov.b64 {%0, %1}, %2;" : "=f"(r.x), "=f"(r.y) : "l"(v));
    return r;
}
__device__ __forceinline__ unsigned long long fma2_(unsigned long long a,
                                                    unsigned long long b,
                                                    unsigned long long c) {
    unsigned long long d;
    asm("fma.rn.f32x2 %0, %1, %2, %3;" : "=l"(d) : "l"(a), "l"(b), "l"(c));
    return d;
}
__device__ __forceinline__ unsigned long long add2_(unsigned long long a,
                                                    unsigned long long b) {
    unsigned long long d;
    asm("add.rn.f32x2 %0, %1, %2;" : "=l"(d) : "l"(a), "l"(b));
    return d;
}

__device__ __forceinline__ float fsig(float x) {
    return __fdividef(1.0f, 1.0f + __expf(-x));
}
__device__ __forceinline__ float ftanh_(float x) {
    x = fminf(fmaxf(x, -15.0f), 15.0f);
    float e = __expf(2.0f * x);
    return __fdividef(e - 1.0f, e + 1.0f);
}

#define MBAR_INIT(addr, cnt) \
    asm volatile("mbarrier.init.shared.b64 [%0], %1;" :: "r"(addr), "r"(cnt) : "memory")
#define MBAR_ARRIVE_EXPECT_TX(addr, tx) \
    asm volatile("mbarrier.arrive.expect_tx.shared.b64 _, [%0], %1;" :: "r"(addr), "r"(tx) : "memory")
#define MBAR_WAIT_PARITY(addr, par) do {                                          \
    uint32_t _mb = (addr); uint32_t _p = (par); uint32_t _done;                   \
    asm volatile("{\n\t.reg .pred p;\n\t"                                         \
        "mbarrier.try_wait.parity.acquire.cta.shared::cta.b64 p, [%1], %2;\n\t"   \
        "selp.b32 %0, 1, 0, p;\n\t}"                                              \
        : "=r"(_done) : "r"(_mb), "r"(_p) : "memory");                            \
    if (!_done) {                                                                 \
        asm volatile("{\n\t.reg .pred P1;\n\t"                                    \
        "WL_%=:\n\t"                                                              \
        "mbarrier.try_wait.parity.acquire.cta.shared::cta.b64 P1, [%0], %1, 0x989680;\n\t" \
        "@P1 bra.uni WD_%=;\n\t"                                                  \
        "bra.uni WL_%=;\n\t"                                                      \
        "WD_%=:\n\t}" :: "r"(_mb), "r"(_p) : "memory");                           \
    }                                                                             \
} while (0)

// ---------------------------------------------------------------------------
// Dummy kernel: shifts the ncu capture window (-s 5 -c 1) so that k_lstm
// lands on the profiled launch slot. Negligible runtime.
// ---------------------------------------------------------------------------
__device__ int g_dummy_sink;
__global__ void k_nop(int v) { if (threadIdx.x == 1025) g_dummy_sink = v; }

// ---------------------------------------------------------------------------
// K1: fused embedding-gather + input GEMM (A duplicated in smem, u64 B pairs).
// ---------------------------------------------------------------------------
__global__ void __launch_bounds__(256, 2)
k_ingemm(const int* __restrict__ text, const float* __restrict__ emb,
         const float* __restrict__ Wf, const float* __restrict__ bf,
         const float* __restrict__ Wb, const float* __restrict__ bb)
{
    extern __shared__ char sm1raw[];
    unsigned long long* As2 = (unsigned long long*)sm1raw;   // 64 x 130 u64
    float* Bs = (float*)(As2 + 64 * 130);                    // 128 x 64 f32
    int*   toks = (int*)(Bs + 128 * 64);                     // 64

    int bx = blockIdx.x, by = blockIdx.y, tid = threadIdx.x;
    const float* W; const float* bias; float* out; int ncol0;
    if (by < 16) { W = Wf; bias = bf; out = g_xzf; ncol0 = by * 64; }
    else         { W = Wb; bias = bb; out = g_xzb; ncol0 = (by - 16) * 64; }

    if (tid < 64) toks[tid] = text[bx * 64 + tid];
    __syncthreads();

    for (int i = tid; i < 2048; i += 256) {
        int m = i >> 5, k4 = i & 31;
        float4 v = __ldg((const float4*)(emb + (size_t)toks[m] * 128) + k4);
        ulonglong2 d0, d1;
        d0.x = pk2(v.x, v.x); d0.y = pk2(v.y, v.y);
        d1.x = pk2(v.z, v.z); d1.y = pk2(v.w, v.w);
        *(ulonglong2*)(As2 + m * 130 + k4 * 4)     = d0;
        *(ulonglong2*)(As2 + m * 130 + k4 * 4 + 2) = d1;
    }
    for (int i = tid; i < 2048; i += 256) {
        int k = i >> 4, n4 = i & 15;
        float4 v = __ldg((const float4*)(W + (size_t)k * 1024 + ncol0) + n4);
        *(float4*)(Bs + k * 64 + n4 * 4) = v;
    }
    __syncthreads();

    int tx = tid & 15, ty = tid >> 4;
    const unsigned long long* Bu = (const unsigned long long*)Bs;
    unsigned long long a01[4], a23[4];
#pragma unroll
    for (int i = 0; i < 4; i++) { a01[i] = 0ULL; a23[i] = 0ULL; }

#pragma unroll 2
    for (int kb = 0; kb < 128; kb += 4) {
        ulonglong2 ar0[4], ar1[4];
#pragma unroll
        for (int i = 0; i < 4; i++) {
            ar0[i] = *(const ulonglong2*)(As2 + (ty * 4 + i) * 130 + kb);
            ar1[i] = *(const ulonglong2*)(As2 + (ty * 4 + i) * 130 + kb + 2);
        }
#pragma unroll
        for (int kq = 0; kq < 4; kq++) {
            ulonglong2 b2 = *(const ulonglong2*)(Bu + (size_t)(kb + kq) * 32 + tx * 2);
#pragma unroll
            for (int i = 0; i < 4; i++) {
                unsigned long long ad = (kq == 0) ? ar0[i].x : (kq == 1) ? ar0[i].y
                                      : (kq == 2) ? ar1[i].x : ar1[i].y;
                a01[i] = fma2_(ad, b2.x, a01[i]);
                a23[i] = fma2_(ad, b2.y, a23[i]);
            }
        }
    }

    float4 bvv = *(const float4*)(bias + ncol0 + tx * 4);
#pragma unroll
    for (int i = 0; i < 4; i++) {
        float2 p01 = unpk2(a01[i]), p23 = unpk2(a23[i]);
        float4 o;
        o.x = p01.x + bvv.x; o.y = p01.y + bvv.y;
        o.z = p23.x + bvv.z; o.w = p23.y + bvv.w;
        *(float4*)(out + (size_t)(bx * 64 + ty * 4 + i) * 1024 + ncol0 + tx * 4) = o;
    }
}

// ---------------------------------------------------------------------------
// GEMM K-slice helper for k_lstm (templated so both slice sizes fully unroll)
// hb: current h buffer, u64 pairs laid out [pair][k] (hb[p*256+k]).
// ---------------------------------------------------------------------------
template <int KCNT>
__device__ __forceinline__ void gemm_slice(const float* Uc,
                                           const unsigned long long* hb,
                                           int k0, int l,
                                           unsigned long long acc[4][4])
{
#pragma unroll
    for (int kk = 0; kk < KCNT; kk += 2) {
        int k = k0 + kk;
        float4 uq0 = *(const float4*)(Uc + k * 128 + l * 4);
        float4 uq1 = *(const float4*)(Uc + (k + 1) * 128 + l * 4);
        unsigned long long u00 = pk2(uq0.x, uq0.x), u01 = pk2(uq0.y, uq0.y);
        unsigned long long u02 = pk2(uq0.z, uq0.z), u03 = pk2(uq0.w, uq0.w);
        unsigned long long u10 = pk2(uq1.x, uq1.x), u11 = pk2(uq1.y, uq1.y);
        unsigned long long u12 = pk2(uq1.z, uq1.z), u13 = pk2(uq1.w, uq1.w);
#pragma unroll
        for (int p = 0; p < 4; p++) {
            ulonglong2 hp = *(const ulonglong2*)(hb + p * 256 + k);  // broadcast
            acc[p][0] = fma2_(hp.x, u00, acc[p][0]);
            acc[p][1] = fma2_(hp.x, u01, acc[p][1]);
            acc[p][2] = fma2_(hp.x, u02, acc[p][2]);
            acc[p][3] = fma2_(hp.x, u03, acc[p][3]);
            acc[p][0] = fma2_(hp.y, u10, acc[p][0]);
            acc[p][1] = fma2_(hp.y, u11, acc[p][1]);
            acc[p][2] = fma2_(hp.y, u12, acc[p][2]);
            acc[p][3] = fma2_(hp.y, u13, acc[p][3]);
        }
    }
}

// ---------------------------------------------------------------------------
// K2: LSTM recurrence. 16 clusters x 8 CTAs. NO per-step cluster barrier:
// h exchange is 32x cp.async.bulk (256B) shared::cta -> shared::cluster with
// mbarrier::complete_tx completion (8192B expected per step per CTA); the
// next step gates on a local mbarrier parity wait only.
// h buffers: hbu[buf][pair][k] u64 (batch pairs packed for FFMA2).
// Consumer warps 0-3 take K-slice 10, GEMM-only warps 4-15 take 18.
// ---------------------------------------------------------------------------
__global__ void __cluster_dims__(8, 1, 1) __launch_bounds__(512, 1)
k_lstm(const float* __restrict__ Uf, const float* __restrict__ Ub)
{
    extern __shared__ float sm2[];
    float* Uc = sm2;                                              // 128KB
    unsigned long long* hbu = (unsigned long long*)(sm2 + 32768); // 2048 u64 = 16KB
    ulonglong2* zpu2 = (ulonglong2*)(hbu + 2048);                 // 4096x16B = 64KB
    unsigned long long* stg = (unsigned long long*)(zpu2 + 4096); // 128 u64 [p][jj] = 1KB
    // mbarriers full[0], full[1] directly after stg
    uint32_t stg_addr  = (uint32_t)__cvta_generic_to_shared(stg);
    uint32_t mbar_addr = stg_addr + 128 * 8;
    uint32_t hbu_addr  = (uint32_t)__cvta_generic_to_shared(hbu);

    int tid = threadIdx.x;
    unsigned rank;
    asm("mov.u32 %0, %%cluster_ctarank;" : "=r"(rank));
    int cl = blockIdx.x >> 3;
    int dir = cl & 1, bg = cl >> 1;
    const float* U    = dir ? Ub     : Uf;
    const float* xz   = dir ? g_xzb  : g_xzf;
    float*       hout = dir ? g_hb   : g_hf;

    int w = tid >> 5, l = tid & 31;

    // Uc[k*128 + unit*4 + g] = U[k*1024 + g*256 + rank*32 + unit]
    for (int idx = tid; idx < 32768; idx += 512) {
        int k = idx >> 7, c = idx & 127;
        int unit = c >> 2, g = c & 3;
        Uc[idx] = __ldg(U + (size_t)k * 1024 + g * 256 + rank * 32 + unit);
    }
    for (int i = tid; i < 2048; i += 512) hbu[i] = 0ULL;
    if (tid == 0) {
        MBAR_INIT(mbar_addr, 1);
        MBAR_INIT(mbar_addr + 8, 1);
    }

    bool cons = (w < 4);
    int bp = w, jj = l;
    int b0 = bg * 8 + 2 * bp, b1 = b0 + 1;
    float cst0 = 0.f, cst1 = 0.f;
    float x[8];

    // bulk-issuer lanes: warp 0, lanes 0-7 (one remote CTA each)
    uint32_t rdst = 0, rmbar = 0;
    bool issuer = (w == 0 && l < 8);
    if (issuer) {
        asm volatile("mapa.shared::cluster.u32 %0, %1, %2;" : "=r"(rdst)  : "r"(hbu_addr),  "r"(l));
        asm volatile("mapa.shared::cluster.u32 %0, %1, %2;" : "=r"(rmbar) : "r"(mbar_addr), "r"(l));
    }
    asm volatile("barrier.cluster.arrive.aligned;\n\tbarrier.cluster.wait.aligned;" ::: "memory");

    int ph0 = 0, ph1 = 0;
    for (int n = 0; n < 512; n++) {
        int cur = n & 1, nxt = cur ^ 1;
        int t = dir ? (511 - n) : n;

        if (n) {
            uint32_t mb = mbar_addr + cur * 8;
            if (cur) { MBAR_WAIT_PARITY(mb, ph1); ph1 ^= 1; }
            else     { MBAR_WAIT_PARITY(mb, ph0); ph0 ^= 1; }
        }
        if (tid == 0 && n < 511)
            MBAR_ARRIVE_EXPECT_TX(mbar_addr + nxt * 8, 8192u);

        // this step's xz (lands during GEMM)
        if (cons) {
            const float* xp0 = xz + ((size_t)b0 * 512 + t) * 1024 + rank * 32 + jj;
            const float* xp1 = xz + ((size_t)b1 * 512 + t) * 1024 + rank * 32 + jj;
            x[0] = __ldg(xp0); x[1] = __ldg(xp0 + 256);
            x[2] = __ldg(xp0 + 512); x[3] = __ldg(xp0 + 768);
            x[4] = __ldg(xp1); x[5] = __ldg(xp1 + 256);
            x[6] = __ldg(xp1 + 512); x[7] = __ldg(xp1 + 768);
        }

        // GEMM (uneven K split: consumers 10, others 18; 4*10+12*18=256)
        const unsigned long long* hb = hbu + cur * 1024;
        unsigned long long acc[4][4];
#pragma unroll
        for (int p = 0; p < 4; p++)
#pragma unroll
            for (int g = 0; g < 4; g++) acc[p][g] = 0ULL;
        if (w < 4) gemm_slice<10>(Uc, hb, w * 10, l, acc);
        else       gemm_slice<18>(Uc, hb, 40 + (w - 4) * 18, l, acc);

#pragma unroll
        for (int p = 0; p < 4; p++) {
            ulonglong2 h0v, h1v;
            h0v.x = acc[p][0]; h0v.y = acc[p][1];
            h1v.x = acc[p][2]; h1v.y = acc[p][3];
            zpu2[((w * 4 + p) * 2 + 0) * 32 + l] = h0v;
            zpu2[((w * 4 + p) * 2 + 1) * 32 + l] = h1v;
        }
        __syncthreads();

        if (cons) {
            unsigned long long s0 = 0ULL, s1 = 0ULL, s2 = 0ULL, s3 = 0ULL;
#pragma unroll
            for (int w2 = 0; w2 < 16; w2++) {
                ulonglong2 a = zpu2[((w2 * 4 + bp) * 2 + 0) * 32 + jj];
                ulonglong2 b = zpu2[((w2 * 4 + bp) * 2 + 1) * 32 + jj];
                s0 = add2_(s0, a.x); s1 = add2_(s1, a.y);
                s2 = add2_(s2, b.x); s3 = add2_(s3, b.y);
            }
            float2 zi = unpk2(s0), zf = unpk2(s1), zg = unpk2(s2), zo = unpk2(s3);
            float i0 = fsig(zi.x + x[0]), f0 = fsig(zf.x + x[1]);
            float g0 = ftanh_(zg.x + x[2]), o0 = fsig(zo.x + x[3]);
            float i1 = fsig(zi.y + x[4]), f1 = fsig(zf.y + x[5]);
            float g1 = ftanh_(zg.y + x[6]), o1 = fsig(zo.y + x[7]);
            cst0 = f0 * cst0 + i0 * g0;
            cst1 = f1 * cst1 + i1 * g1;
            float h0new = o0 * ftanh_(cst0);
            float h1new = o1 * ftanh_(cst1);
            stg[bp * 32 + jj] = pk2(h0new, h1new);   // lane-stride 8B, CF

            // consumer-warps-only barrier (id 1, 128 threads)
            asm volatile("bar.sync 1, 128;" ::: "memory");

            if (issuer && n < 511) {
                asm volatile("fence.proxy.async.shared::cta;" ::: "memory");
#pragma unroll
                for (int p = 0; p < 4; p++) {
                    uint32_t dst = rdst + (uint32_t)(((nxt * 4 + p) * 256 + rank * 32) * 8);
                    uint32_t src = stg_addr + (uint32_t)(p * 256);
                    asm volatile(
                        "cp.async.bulk.shared::cluster.shared::cta.mbarrier::complete_tx::bytes "
                        "[%0], [%1], %2, [%3];"
                        :: "r"(dst), "r"(src), "r"(256u), "r"(rmbar + nxt * 8)
                        : "memory");
                }
            }
            // off the critical path: global h stores
            hout[((size_t)b0 * 512 + t) * 256 + rank * 32 + jj] = h0new;
            hout[((size_t)b1 * 512 + t) * 256 + rank * 32 + jj] = h1new;
        }
    }
}

// ---------------------------------------------------------------------------
// K3: logits = [h_fwd ; h_bwd] @ W_d + b_d.  Warp per row, W_d^T in smem.
// ---------------------------------------------------------------------------
__global__ void k_logits(const float* __restrict__ Wd, const float* __restrict__ bd,
                         float* __restrict__ out)
{
    __shared__ float Wds[NTAGS_ * 512];
    __shared__ float bds[NTAGS_];
    int tid = threadIdx.x;
    for (int i = tid; i < 512 * NTAGS_; i += 256) {
        int k = i / NTAGS_, c = i - k * NTAGS_;
        Wds[c * 512 + k] = Wd[i];
    }
    if (tid < NTAGS_) bds[tid] = bd[tid];
    __syncthreads();

    int wid = tid >> 5, l = tid & 31;
    int r = blockIdx.x * 8 + wid;
    const float* pf = g_hf + (size_t)r * 256 + l;
    const float* pb = g_hb + (size_t)r * 256 + l;
    float hf[8], hbv[8];
#pragma unroll
    for (int i = 0; i < 8; i++) { hf[i] = pf[32 * i]; hbv[i] = pb[32 * i]; }

    float parts[NTAGS_];
#pragma unroll
    for (int c = 0; c < NTAGS_; c++) {
        float p = 0.f;
#pragma unroll
        for (int i = 0; i < 8; i++) {
            p = fmaf(hf[i],  Wds[c * 512 + 32 * i + l], p);
            p = fmaf(hbv[i], Wds[c * 512 + 256 + 32 * i + l], p);
        }
        parts[c] = p;
    }
#pragma unroll
    for (int c = 0; c < NTAGS_; c++)
#pragma unroll
        for (int off = 16; off; off >>= 1)
            parts[c] += __shfl_xor_sync(0xffffffffu, parts[c], off);

    if (l == 0) {
#pragma unroll
        for (int c = 0; c < NTAGS_; c++)
            out[(size_t)r * NTAGS_ + c] = parts[c] + bds[c];
    }
}

// ---------------------------------------------------------------------------
// K4: lens + CRF.  One warp per batch element; fast-math exp/log.
// ---------------------------------------------------------------------------
__global__ void k_crf(const int* __restrict__ text, const int* __restrict__ labels,
                      const float* __restrict__ trans, float* __restrict__ out)
{
    int b = blockIdx.x;
    int l = threadIdx.x;
    const float* lgb = out + (size_t)b * NS_ * NTAGS_;
    const int*   lab = labels + b * NS_;

    int cnt = 0;
#pragma unroll
    for (int i = 0; i < 16; i++) cnt += (text[b * NS_ + l + 32 * i] != 0) ? 1 : 0;
#pragma unroll
    for (int off = 16; off; off >>= 1) cnt += __shfl_xor_sync(0xffffffffu, cnt, off);
    int len = cnt;
    if (l == 0) out[LENS_OFF + b] = (float)len;

    float sc = 0.f;
#pragma unroll
    for (int i = 0; i < 16; i++) {
        int s = l + 32 * i;
        if (s < len)     sc += lgb[s * NTAGS_ + lab[s]];
        if (s < len - 1) sc += trans[lab[s] * NTAGS_ + lab[s + 1]];
    }
#pragma unroll
    for (int off = 16; off; off >>= 1) sc += __shfl_xor_sync(0xffffffffu, sc, off);

    int j = l;
    float tc[NTAGS_];
#pragma unroll
    for (int i = 0; i < NTAGS_; i++) tc[i] = trans[i * NTAGS_ + ((j < NTAGS_) ? j : 0)];
    float alpha = (j < NTAGS_) ? lgb[j] : -3.0e38f;

    float lt_next = (j < NTAGS_) ? lgb[NTAGS_ + j] : 0.f;
    for (int t = 1; t < NS_; t++) {
        float lt = lt_next;
        if (t + 1 < NS_) lt_next = (j < NTAGS_) ? lgb[(t + 1) * NTAGS_ + j] : 0.f;
        float vv[NTAGS_];
#pragma unroll
        for (int i = 0; i < NTAGS_; i++) {
            float ai = __shfl_sync(0xffffffffu, alpha, i);
            vv[i] = ai + tc[i];
        }
        float m01 = fmaxf(vv[0], vv[1]), m23 = fmaxf(vv[2], vv[3]);
        float m45 = fmaxf(vv[4], vv[5]), m67 = fmaxf(vv[6], vv[7]);
        float m03 = fmaxf(m01, m23), m47 = fmaxf(m45, m67);
        float mx = fmaxf(fmaxf(m03, m47), vv[8]);
        float e0 = __expf(vv[0] - mx) + __expf(vv[1] - mx);
        float e1 = __expf(vv[2] - mx) + __expf(vv[3] - mx);
        float e2 = __expf(vv[4] - mx) + __expf(vv[5] - mx);
        float e3 = __expf(vv[6] - mx) + __expf(vv[7] - mx);
        float sume = ((e0 + e1) + (e2 + e3)) + __expf(vv[8] - mx);
        float na = mx + __logf(sume) + lt;
        if ((t < len) && (j < NTAGS_)) alpha = na;
    }

    float a = (j < NTAGS_) ? alpha : -3.0e38f;
    float mx = a;
#pragma unroll
    for (int off = 16; off; off >>= 1) mx = fmaxf(mx, __shfl_xor_sync(0xffffffffu, mx, off));
    float e = (j < NTAGS_) ? __expf(a - mx) : 0.f;
#pragma unroll
    for (int off = 16; off; off >>= 1) e += __shfl_xor_sync(0xffffffffu, e, off);
    float lse = mx + __logf(e);

    if (l == 0) out[LL_OFF + b] = sc - lse;
}

// ---------------------------------------------------------------------------
extern "C" void kernel_launch(void* const* d_in, const int* in_sizes, int n_in,
                              void* d_out, int out_size)
{
    (void)in_sizes; (void)n_in; (void)out_size;
    const int*   text   = (const int*)d_in[0];
    const int*   labels = (const int*)d_in[1];
    const float* emb    = (const float*)d_in[2];
    const float* Wf     = (const float*)d_in[3];
    const float* Uf     = (const float*)d_in[4];
    const float* bf     = (const float*)d_in[5];
    const float* Wb     = (const float*)d_in[6];
    const float* Ub     = (const float*)d_in[7];
    const float* bb     = (const float*)d_in[8];
    const float* Wd     = (const float*)d_in[9];
    const float* bd     = (const float*)d_in[10];
    const float* trans  = (const float*)d_in[11];
    float* out = (float*)d_out;

    int smem1 = 64 * 130 * 8 + 128 * 64 * 4 + 64 * 4;               // 99584 B
    cudaFuncSetAttribute(k_ingemm, cudaFuncAttributeMaxDynamicSharedMemorySize, smem1);
    int smem2 = 32768 * 4 + 2048 * 8 + 4096 * 16 + 128 * 8 + 64;    // ~214 KB
    cudaFuncSetAttribute(k_lstm, cudaFuncAttributeMaxDynamicSharedMemorySize, smem2);

    k_ingemm<<<dim3(512, 32), 256, smem1>>>(text, emb, Wf, bf, Wb, bb);
    // two dummy launches keep the ncu capture slot (-s 5 -c 1) on k_lstm
    k_nop<<<1, 32>>>(0);
    k_nop<<<1, 32>>>(1);
    k_lstm<<<128, 512, smem2>>>(Uf, Ub);
    k_logits<<<4096, 256>>>(Wd, bd, out);
    k_crf<<<NB_, 32>>>(text, labels, trans, out);
}